// round 8
// baseline (speedup 1.0000x reference)
#include <cuda_runtime.h>
#include <math.h>
#include <stdint.h>

#define NPB 65536
#define NT  131072

// ---------------- scratch ----------
__device__ float g_X [NT*64];
__device__ float g_Mk[NT*64];
__device__ float g_Q [NT*64];
__device__ float g_K [NT*64];
__device__ float g_V [NT*64];
__device__ float g_T1[NT*64];
__device__ float g_H1[NT*256];
__device__ float g_GP[2*512*1152];
__device__ float g_GS[2304];
__device__ float g_MC[2*64*64];

__device__ __forceinline__ float gelu_f(float u){
    return 0.5f*u*(1.f+erff(u*0.70710678118654752f));
}
__device__ __forceinline__ uint32_t tf32c(float f){
    uint32_t r; asm("cvt.rna.tf32.f32 %0, %1;" : "=r"(r) : "f"(f)); return r;
}
#define MMA_TF32(d, a, b0, b1) \
  asm volatile("mma.sync.aligned.m16n8k8.row.col.f32.tf32.tf32.f32 " \
    "{%0,%1,%2,%3},{%4,%5,%6,%7},{%8,%9},{%0,%1,%2,%3};" \
    : "+f"((d)[0]),"+f"((d)[1]),"+f"((d)[2]),"+f"((d)[3]) \
    : "r"((a)[0]),"r"((a)[1]),"r"((a)[2]),"r"((a)[3]),"r"(b0),"r"(b1))

#define XS_STRIDE 68
#define WS_STRIDE 72
#define XS_U (128*XS_STRIDE)
#define WS_U (64*WS_STRIDE)
#define TM_SMEM ((XS_U + WS_U + 64)*4)

// ---------------- tf32 tensor GEMM -----------------------------------------
// Tile 128px(M) x 64out(N), K=64/chunk. 128 threads = 4 warps.
// KC: K chunks (acc persists). NC: N chunks. MODE: 0 store,1 gelu,2 add.
// FUSE: 0 plain, 1 LayerNorm on X during staging (xa=gamma,xb=beta),
//       2 depthwise3x3+GELU on X during staging (xa=dw weights [9][xStride]).
template<int KC,int NC,int MODE,int FUSE>
__global__ __launch_bounds__(128, 4) void k_tmma(
        const float* __restrict__ X, int xStride,
        const float* __restrict__ W, int wStride, int wBatchStride,
        const float* __restrict__ bias,
        const float* __restrict__ xa, const float* __restrict__ xb,
        float* __restrict__ OUT, int oStride){
    extern __shared__ uint32_t smu[];
    uint32_t* xs = smu;
    uint32_t* ws = smu + XS_U;
    float*    sb = (float*)(smu + XS_U + WS_U);
    const int t = threadIdx.x;
    const int warp = t>>5, lane = t&31;
    const int lr = lane>>2, lc = lane&3;
    const int m0 = warp*32;
    const int c4f = t&15;
    const size_t tileBase = (size_t)blockIdx.x*128;
    const float* Wb = W + (wBatchStride ? (int)(tileBase>>16)*(size_t)wBatchStride : 0);
    if(bias && t<64) sb[t] = bias[t];

    float4 g4, b4;
    if(FUSE==1){
        g4 = *(const float4*)(xa + c4f*4);
        b4 = *(const float4*)(xb + c4f*4);
    }

    float acc[64];
    const int CH = (KC>NC)?KC:NC;

    for(int c=0;c<CH;c++){
        const int kOff = (KC>1)? c*64 : 0;
        const int nOff = (NC>1)? c*64 : 0;
        if(c) __syncthreads();
        if(c==0 || KC>1){
            if(FUSE==2){
                float4 wv9[9];
                #pragma unroll
                for(int q9=0;q9<9;q9++)
                    wv9[q9] = *(const float4*)(xa + q9*xStride + kOff + c4f*4);
                #pragma unroll
                for(int it=0;it<16;it++){
                    int p = it*8 + (t>>4);
                    size_t pg = tileBase + p;
                    int b=(int)(pg>>16), pp=(int)(pg&65535), y=pp>>8, x=pp&255;
                    float4 cv = make_float4(0,0,0,0);
                    #pragma unroll
                    for(int dy=0;dy<3;dy++){
                        int yy=y+dy-1; if(yy<0||yy>255) continue;
                        #pragma unroll
                        for(int dx=0;dx<3;dx++){
                            int xx=x+dx-1; if(xx<0||xx>255) continue;
                            float4 hv = *(const float4*)(X +
                                ((((size_t)b<<16)+(yy<<8)+xx))*(size_t)xStride + kOff + c4f*4);
                            float4 w9 = wv9[dy*3+dx];
                            cv.x+=hv.x*w9.x; cv.y+=hv.y*w9.y;
                            cv.z+=hv.z*w9.z; cv.w+=hv.w*w9.w;
                        }
                    }
                    uint32_t* xr = xs + p*XS_STRIDE + c4f*4;
                    xr[0]=tf32c(gelu_f(cv.x)); xr[1]=tf32c(gelu_f(cv.y));
                    xr[2]=tf32c(gelu_f(cv.z)); xr[3]=tf32c(gelu_f(cv.w));
                }
            } else {
                #pragma unroll
                for(int it=0;it<16;it++){
                    int s4 = t + it*128;
                    int p = s4>>4, c4 = s4&15;
                    float4 v = *(const float4*)(X + (tileBase+p)*(size_t)xStride + kOff + c4*4);
                    if(FUSE==1){
                        float s1 = v.x+v.y+v.z+v.w;
                        float s2 = v.x*v.x+v.y*v.y+v.z*v.z+v.w*v.w;
                        #pragma unroll
                        for(int sw=1;sw<16;sw<<=1){
                            s1 += __shfl_xor_sync(0xffffffffu, s1, sw);
                            s2 += __shfl_xor_sync(0xffffffffu, s2, sw);
                        }
                        float mu = s1*(1.f/64.f);
                        float var = fmaxf(s2*(1.f/64.f) - mu*mu, 0.f);
                        float rs = rsqrtf(var + 1e-5f);
                        v.x = (v.x-mu)*rs*g4.x + b4.x;
                        v.y = (v.y-mu)*rs*g4.y + b4.y;
                        v.z = (v.z-mu)*rs*g4.z + b4.z;
                        v.w = (v.w-mu)*rs*g4.w + b4.w;
                    }
                    uint32_t* xr = xs + p*XS_STRIDE + c4*4;
                    xr[0]=tf32c(v.x); xr[1]=tf32c(v.y); xr[2]=tf32c(v.z); xr[3]=tf32c(v.w);
                }
            }
        }
        #pragma unroll
        for(int it=0;it<32;it++){
            int s = t + it*128;
            int o = s&63, j = s>>6;
            ws[j*WS_STRIDE+o] = tf32c(Wb[(size_t)(kOff+j)*wStride + nOff + o]);
        }
        __syncthreads();
        if(c==0 || NC>1){
            if(bias){
                #pragma unroll
                for(int mt=0;mt<2;mt++)
                    #pragma unroll
                    for(int j=0;j<8;j++){
                        float b0 = sb[j*8 + 2*lc], b1 = sb[j*8 + 2*lc + 1];
                        acc[mt*32+j*4+0]=b0; acc[mt*32+j*4+1]=b1;
                        acc[mt*32+j*4+2]=b0; acc[mt*32+j*4+3]=b1;
                    }
            } else {
                #pragma unroll
                for(int q=0;q<64;q++) acc[q]=0.f;
            }
        }
        #pragma unroll
        for(int k0=0;k0<64;k0+=8){
            uint32_t a[2][4];
            #pragma unroll
            for(int mt=0;mt<2;mt++){
                const uint32_t* xbp = xs + (m0+mt*16+lr)*XS_STRIDE + k0 + lc;
                a[mt][0]=xbp[0]; a[mt][1]=xbp[8*XS_STRIDE];
                a[mt][2]=xbp[4]; a[mt][3]=xbp[8*XS_STRIDE+4];
            }
            #pragma unroll
            for(int j=0;j<8;j++){
                uint32_t b0 = ws[(k0+lc  )*WS_STRIDE + j*8 + lr];
                uint32_t b1 = ws[(k0+lc+4)*WS_STRIDE + j*8 + lr];
                MMA_TF32(acc +      j*4, a[0], b0, b1);
                MMA_TF32(acc + 32 + j*4, a[1], b0, b1);
            }
        }
        if(NC>1 || c==CH-1){
            #pragma unroll
            for(int mt=0;mt<2;mt++){
                #pragma unroll
                for(int j=0;j<8;j++){
                    size_t row = tileBase + m0 + mt*16 + lr;
                    int col = nOff + j*8 + 2*lc;
                    float v0=acc[mt*32+j*4], v1=acc[mt*32+j*4+1];
                    float v2=acc[mt*32+j*4+2], v3=acc[mt*32+j*4+3];
                    if(MODE==1){ v0=gelu_f(v0); v1=gelu_f(v1); v2=gelu_f(v2); v3=gelu_f(v3); }
                    float* p0 = OUT + row*(size_t)oStride + col;
                    float* p8 = p0 + 8*(size_t)oStride;
                    if(MODE==2){
                        float2 o0 = *(float2*)p0, o8 = *(float2*)p8;
                        v0+=o0.x; v1+=o0.y; v2+=o8.x; v3+=o8.y;
                    }
                    *(float2*)p0 = make_float2(v0,v1);
                    *(float2*)p8 = make_float2(v2,v3);
                }
            }
        }
    }
}

// ---------------- fused QK gemm + gram partials ----------------------------
// Per block: 128 px. Q=X@Wq, K=X@Wk via mma, dumped to smem fp32,
// then per-head 16x16 gram partial + channel norms -> gpart[b][tile][1152].
#define QG_SMEM ((XS_U + WS_U + XS_U)*4)
__global__ __launch_bounds__(128, 2) void k_qkgram(
        const float* __restrict__ X,
        const float* __restrict__ Wq, const float* __restrict__ Wk,
        float* __restrict__ gpart){
    extern __shared__ uint32_t smu[];
    uint32_t* xs = smu;             // tf32 X, later fp32 K
    uint32_t* ws = smu + XS_U;
    float*    qT = (float*)(smu + XS_U + WS_U);  // fp32 Q
    const int t = threadIdx.x;
    const int warp = t>>5, lane = t&31;
    const int lr = lane>>2, lc = lane&3;
    const int m0 = warp*32;
    const size_t tileBase = (size_t)blockIdx.x*128;

    // stage X
    #pragma unroll
    for(int it=0;it<16;it++){
        int s4 = t + it*128;
        int p = s4>>4, c4 = s4&15;
        float4 v = *(const float4*)(X + (tileBase+p)*64 + c4*4);
        uint32_t* xr = xs + p*XS_STRIDE + c4*4;
        xr[0]=tf32c(v.x); xr[1]=tf32c(v.y); xr[2]=tf32c(v.z); xr[3]=tf32c(v.w);
    }

    float acc[64];
    auto stageW = [&](const float* Wm){
        #pragma unroll
        for(int it=0;it<32;it++){
            int s = t + it*128;
            int o = s&63, j = s>>6;
            ws[j*WS_STRIDE+o] = tf32c(Wm[j*64 + o]);
        }
    };
    auto runMMA = [&](){
        #pragma unroll
        for(int q=0;q<64;q++) acc[q]=0.f;
        #pragma unroll
        for(int k0=0;k0<64;k0+=8){
            uint32_t a[2][4];
            #pragma unroll
            for(int mt=0;mt<2;mt++){
                const uint32_t* xbp = xs + (m0+mt*16+lr)*XS_STRIDE + k0 + lc;
                a[mt][0]=xbp[0]; a[mt][1]=xbp[8*XS_STRIDE];
                a[mt][2]=xbp[4]; a[mt][3]=xbp[8*XS_STRIDE+4];
            }
            #pragma unroll
            for(int j=0;j<8;j++){
                uint32_t b0 = ws[(k0+lc  )*WS_STRIDE + j*8 + lr];
                uint32_t b1 = ws[(k0+lc+4)*WS_STRIDE + j*8 + lr];
                MMA_TF32(acc +      j*4, a[0], b0, b1);
                MMA_TF32(acc + 32 + j*4, a[1], b0, b1);
            }
        }
    };
    auto dump = [&](float* dst){
        #pragma unroll
        for(int mt=0;mt<2;mt++)
            #pragma unroll
            for(int j=0;j<8;j++){
                int row = m0+mt*16+lr, col = j*8+2*lc;
                dst[row*XS_STRIDE+col]   = acc[mt*32+j*4+0];
                dst[row*XS_STRIDE+col+1] = acc[mt*32+j*4+1];
                dst[(row+8)*XS_STRIDE+col]   = acc[mt*32+j*4+2];
                dst[(row+8)*XS_STRIDE+col+1] = acc[mt*32+j*4+3];
            }
    };

    stageW(Wq);
    __syncthreads();
    runMMA();
    dump(qT);
    __syncthreads();           // Q dumped; all ws reads done
    stageW(Wk);
    __syncthreads();
    runMMA();                  // K in acc
    __syncthreads();           // all xs (X) reads done
    dump((float*)xs);          // overwrite xs with fp32 K
    __syncthreads();

    // gram: head per warp; thread covers d in {db,db+1}, e in {eb..eb+3}
    const float* kf = (float*)xs;
    const int h = warp;
    const int tt = lane;
    const int db = (tt&7)*2, eb = (tt>>3)*4;
    float s00=0,s01=0,s02=0,s03=0,s10=0,s11=0,s12=0,s13=0;
    float nrm = 0.f;
    const int nc = t&63;
    const float* nf = (t<64)? qT : kf;
    #pragma unroll 4
    for(int p=0;p<128;p++){
        const float* qr = qT + p*XS_STRIDE + h*16;
        const float* kr = kf + p*XS_STRIDE + h*16;
        float k0v = kr[db], k1v = kr[db+1];
        float q0 = qr[eb], q1 = qr[eb+1], q2 = qr[eb+2], q3 = qr[eb+3];
        s00 += k0v*q0; s01 += k0v*q1; s02 += k0v*q2; s03 += k0v*q3;
        s10 += k1v*q0; s11 += k1v*q1; s12 += k1v*q2; s13 += k1v*q3;
        float nv = nf[p*XS_STRIDE + nc];
        nrm += nv*nv;
    }
    float* gp = gpart + (size_t)blockIdx.x*1152;
    float* gs = gp + h*256 + db*16 + eb;
    gs[0]=s00; gs[1]=s01; gs[2]=s02; gs[3]=s03;
    gs[16]=s10; gs[17]=s11; gs[18]=s12; gs[19]=s13;
    gp[1024+t] = nrm;
}

// ---------------- gram reduction over tiles --------------------------------
__global__ __launch_bounds__(128) void k_gred(const float* __restrict__ gpart,
        float* __restrict__ outr){
    int j = blockIdx.x*128 + threadIdx.x;
    int b = blockIdx.y;
    float acc = 0.f;
    const float* gp = gpart + (size_t)b*512*1152 + j;
    for(int tile=0;tile<512;tile++) acc += gp[(size_t)tile*1152];
    outr[b*1152 + j] = acc;
}

// ---------------- attn softmax + fold into Mcomb ---------------------------
__global__ __launch_bounds__(256) void k_attn(const float* __restrict__ sredg,
        const float* __restrict__ Wp, const float* __restrict__ resc,
        float* __restrict__ Mcomb){
    __shared__ float sred[2304];
    __shared__ float sa[2048];
    int tid = threadIdx.x;
    for(int jj=tid;jj<2304;jj+=256) sred[jj]=sredg[jj];
    __syncthreads();
    if(tid<128){
        int b=tid>>6, hd=tid&63, h=hd>>4, d=hd&15;
        float nk = fmaxf(sqrtf(sred[b*1152+1088+hd]),1e-6f);
        float r = resc[h];
        float row[16]; float mx=-1e30f;
        #pragma unroll
        for(int e=0;e<16;e++){
            float nq = fmaxf(sqrtf(sred[b*1152+1024+h*16+e]),1e-6f);
            float v = sred[b*1152 + h*256 + d*16 + e] / (nk*nq) * r;
            row[e]=v; mx=fmaxf(mx,v);
        }
        float s=0.f;
        #pragma unroll
        for(int e=0;e<16;e++){ row[e]=expf(row[e]-mx); s+=row[e]; }
        float inv=1.f/s;
        #pragma unroll
        for(int e=0;e<16;e++) sa[((b*4+h)*16+d)*16+e] = row[e]*inv;
    }
    __syncthreads();
    for(int job=tid;job<8192;job+=256){
        int b=job>>12, rem=job&4095, ci=rem>>6, co=rem&63;
        int h=ci>>4, e=ci&15;
        float acc=0.f;
        #pragma unroll
        for(int d=0;d<16;d++) acc += sa[((b*4+h)*16+d)*16+e] * Wp[(h*16+d)*64+co];
        Mcomb[job]=acc;
    }
}

// ---------------- transposes ----------------
__global__ __launch_bounds__(256) void k_nchw2nhwc(const float* __restrict__ in, float* __restrict__ out){
    __shared__ float t[32][33];
    int tx = threadIdx.x & 31, ty = threadIdx.x >> 5;
    int pt = blockIdx.x, ct = blockIdx.y, b = blockIdx.z;
    const float* ip = in  + (size_t)b*64*NPB;
    float*       op = out + (size_t)b*NPB*64;
    #pragma unroll
    for(int r=0;r<4;r++){
        int c = ct*32 + ty + r*8;
        t[ty+r*8][tx] = ip[(size_t)c*NPB + (size_t)pt*32 + tx];
    }
    __syncthreads();
    #pragma unroll
    for(int r=0;r<4;r++){
        int p = pt*32 + ty + r*8;
        op[(size_t)p*64 + ct*32 + tx] = t[tx][ty+r*8];
    }
}
__global__ __launch_bounds__(256) void k_nhwc2nchw(const float* __restrict__ in, float* __restrict__ out){
    __shared__ float t[32][33];
    int tx = threadIdx.x & 31, ty = threadIdx.x >> 5;
    int pt = blockIdx.x, ct = blockIdx.y, b = blockIdx.z;
    const float* ip = in  + (size_t)b*NPB*64;
    float*       op = out + (size_t)b*64*NPB;
    #pragma unroll
    for(int r=0;r<4;r++){
        int p = pt*32 + ty + r*8;
        t[ty+r*8][tx] = ip[(size_t)p*64 + ct*32 + tx];
    }
    __syncthreads();
    #pragma unroll
    for(int r=0;r<4;r++){
        int c = ct*32 + ty + r*8;
        op[(size_t)c*NPB + (size_t)pt*32 + tx] = t[tx][ty+r*8];
    }
}

// ---------------- mask gate (float4) ---------------------------------------
__global__ __launch_bounds__(256) void k_maskgate(const float* __restrict__ T,
        const float* __restrict__ M1, const float* __restrict__ V,
        const float* __restrict__ dw, const float* __restrict__ db,
        float* __restrict__ VG){
    __shared__ float4 sdw[400];
    __shared__ float4 sdb4[16];
    int tid=threadIdx.x;
    for(int i=tid;i<400;i+=256) sdw[i]=((const float4*)dw)[i];
    if(tid<16) sdb4[tid]=((const float4*)db)[tid];
    __syncthreads();
    size_t e=(size_t)blockIdx.x*256+tid;
    int c4=(int)(e&15);
    size_t p=e>>4;
    int b=(int)(p>>16);
    int pp=(int)(p&65535);
    int y=pp>>8, x=pp&255;
    float4 conv=make_float4(0,0,0,0);
    #pragma unroll
    for(int dy=0;dy<5;dy++){
        int yy=y+dy-2; if(yy<0||yy>255) continue;
        #pragma unroll
        for(int dx=0;dx<5;dx++){
            int xx=x+dx-2; if(xx<0||xx>255) continue;
            float4 tv = *(const float4*)(T + (((((size_t)b<<16)+(yy<<8)+xx)<<6)+c4*4));
            float4 wv = sdw[(dy*5+dx)*16+c4];
            conv.x+=tv.x*wv.x; conv.y+=tv.y*wv.y; conv.z+=tv.z*wv.z; conv.w+=tv.w*wv.w;
        }
    }
    float4 bb=sdb4[c4];
    float4 m1=((const float4*)M1)[e];
    float4 vv=((const float4*)V)[e];
    float4 r;
    r.x = vv.x*m1.x*(1.f+1.f/(1.f+expf(-(conv.x+bb.x))));
    r.y = vv.y*m1.y*(1.f+1.f/(1.f+expf(-(conv.y+bb.y))));
    r.z = vv.z*m1.z*(1.f+1.f/(1.f+expf(-(conv.z+bb.z))));
    r.w = vv.w*m1.w*(1.f+1.f/(1.f+expf(-(conv.w+bb.w))));
    ((float4*)VG)[e]=r;
}

// ---------------- depthwise 3x3 + GELU (float4, 64ch) ----------------------
__global__ __launch_bounds__(256) void k_dw3_gelu(const float* __restrict__ in,
        const float* __restrict__ dw, float* __restrict__ out){
    __shared__ float4 sdw[144];
    int tid=threadIdx.x;
    if(tid<144) sdw[tid]=((const float4*)dw)[tid];
    __syncthreads();
    size_t e=(size_t)blockIdx.x*256+tid;
    int c4=(int)(e&15);
    size_t p=e>>4;
    int b=(int)(p>>16), pp=(int)(p&65535), y=pp>>8, x=pp&255;
    float4 conv=make_float4(0,0,0,0);
    #pragma unroll
    for(int dy=0;dy<3;dy++){
        int yy=y+dy-1; if(yy<0||yy>255) continue;
        #pragma unroll
        for(int dx=0;dx<3;dx++){
            int xx=x+dx-1; if(xx<0||xx>255) continue;
            float4 tv = *(const float4*)(in + (((((size_t)b<<16)+(yy<<8)+xx)<<6)+c4*4));
            float4 wv = sdw[(dy*3+dx)*16+c4];
            conv.x+=tv.x*wv.x; conv.y+=tv.y*wv.y; conv.z+=tv.z*wv.z; conv.w+=tv.w*wv.w;
        }
    }
    float4 r=make_float4(gelu_f(conv.x),gelu_f(conv.y),gelu_f(conv.z),gelu_f(conv.w));
    ((float4*)out)[e]=r;
}

// ---------------- msa epilogue: X += dw3(P, pe2) (float4) ------------------
__global__ __launch_bounds__(256) void k_msa_out(
        const float* __restrict__ P, const float* __restrict__ pe2,
        float* __restrict__ X){
    __shared__ float4 sdw[144];
    int tid=threadIdx.x;
    if(tid<144) sdw[tid]=((const float4*)pe2)[tid];
    __syncthreads();
    size_t e=(size_t)blockIdx.x*256+tid;
    int c4=(int)(e&15);
    size_t p=e>>4;
    int b=(int)(p>>16), pp=(int)(p&65535), y=pp>>8, x=pp&255;
    float4 conv=make_float4(0,0,0,0);
    #pragma unroll
    for(int dy=0;dy<3;dy++){
        int yy=y+dy-1; if(yy<0||yy>255) continue;
        #pragma unroll
        for(int dx=0;dx<3;dx++){
            int xx=x+dx-1; if(xx<0||xx>255) continue;
            float4 tv = *(const float4*)(P + (((((size_t)b<<16)+(yy<<8)+xx)<<6)+c4*4));
            float4 wv = sdw[(dy*3+dx)*16+c4];
            conv.x+=tv.x*wv.x; conv.y+=tv.y*wv.y; conv.z+=tv.z*wv.z; conv.w+=tv.w*wv.w;
        }
    }
    float4 xv=((float4*)X)[e];
    xv.x+=conv.x; xv.y+=conv.y; xv.z+=conv.z; xv.w+=conv.w;
    ((float4*)X)[e]=xv;
}

// ---------------- host -----------------------------------------------------
extern "C" void kernel_launch(void* const* d_in, const int* in_sizes, int n_in,
                              void* d_out, int out_size){
    const float* x    = (const float*)d_in[0];
    const float* mask = (const float*)d_in[1];
    const float* Wq   = (const float*)d_in[2];
    const float* Wk   = (const float*)d_in[3];
    const float* Wv   = (const float*)d_in[4];
    const float* resc = (const float*)d_in[5];
    const float* Wp   = (const float*)d_in[6];
    const float* bp   = (const float*)d_in[7];
    const float* pe1  = (const float*)d_in[8];
    const float* pe2  = (const float*)d_in[9];
    const float* mw1  = (const float*)d_in[10];
    const float* mb1  = (const float*)d_in[11];
    const float* mw2  = (const float*)d_in[12];
    const float* mb2  = (const float*)d_in[13];
    const float* mdw  = (const float*)d_in[14];
    const float* mdb  = (const float*)d_in[15];
    const float* lng  = (const float*)d_in[16];
    const float* lnb  = (const float*)d_in[17];
    const float* fw1  = (const float*)d_in[18];
    const float* fdw  = (const float*)d_in[19];
    const float* fw2  = (const float*)d_in[20];
    float* out = (float*)d_out;

    float *pX,*pM,*pQ,*pK,*pV,*pT1,*pH1,*pGP,*pGS,*pMC;
    cudaGetSymbolAddress((void**)&pX,  g_X);
    cudaGetSymbolAddress((void**)&pM,  g_Mk);
    cudaGetSymbolAddress((void**)&pQ,  g_Q);
    cudaGetSymbolAddress((void**)&pK,  g_K);
    cudaGetSymbolAddress((void**)&pV,  g_V);
    cudaGetSymbolAddress((void**)&pT1, g_T1);
    cudaGetSymbolAddress((void**)&pH1, g_H1);
    cudaGetSymbolAddress((void**)&pGP, g_GP);
    cudaGetSymbolAddress((void**)&pGS, g_GS);
    cudaGetSymbolAddress((void**)&pMC, g_MC);

    cudaFuncSetAttribute(k_tmma<1,1,0,0>, cudaFuncAttributeMaxDynamicSharedMemorySize, TM_SMEM);
    cudaFuncSetAttribute(k_tmma<1,1,2,0>, cudaFuncAttributeMaxDynamicSharedMemorySize, TM_SMEM);
    cudaFuncSetAttribute(k_tmma<1,4,1,1>, cudaFuncAttributeMaxDynamicSharedMemorySize, TM_SMEM);
    cudaFuncSetAttribute(k_tmma<4,1,2,2>, cudaFuncAttributeMaxDynamicSharedMemorySize, TM_SMEM);
    cudaFuncSetAttribute(k_qkgram, cudaFuncAttributeMaxDynamicSharedMemorySize, QG_SMEM);

    dim3 tg(2048,2,2);
    k_nchw2nhwc<<<tg,256>>>(x,    pX);
    k_nchw2nhwc<<<tg,256>>>(mask, pM);

    for(int i=0;i<3;i++){
        const float* Wq_i  = Wq  + i*4096;
        const float* Wk_i  = Wk  + i*4096;
        const float* Wv_i  = Wv  + i*4096;
        const float* Wp_i  = Wp  + i*4096;
        const float* mw1_i = mw1 + i*4096;
        const float* mw2_i = mw2 + i*4096;
        const float* bp_i  = bp  + i*64;
        const float* mb1_i = mb1 + i*64;
        const float* mb2_i = mb2 + i*64;
        const float* mdb_i = mdb + i*64;
        const float* lng_i = lng + i*64;
        const float* lnb_i = lnb + i*64;
        const float* pe1_i = pe1 + i*576;
        const float* pe2_i = pe2 + i*576;
        const float* mdw_i = mdw + i*1600;
        const float* rs_i  = resc+ i*4;
        const float* fw1_i = fw1 + i*64*256;
        const float* fdw_i = fdw + i*9*256;
        const float* fw2_i = fw2 + i*256*64;

        // fused attention stats
        k_qkgram<<<1024,128,QG_SMEM>>>(pX, Wq_i, Wk_i, pGP);
        k_gred<<<dim3(9,2),128>>>(pGP, pGS);
        k_attn<<<1,256>>>(pGS, Wp_i, rs_i, pMC);
        // v + mask gate
        k_tmma<1,1,0,0><<<1024,128,TM_SMEM>>>(pX, 64, Wv_i, 64, 0, nullptr, nullptr, nullptr, pV, 64);
        k_tmma<1,1,0,0><<<1024,128,TM_SMEM>>>(pM, 64, mw1_i, 64, 0, mb1_i, nullptr, nullptr, pT1, 64);
        k_tmma<1,1,0,0><<<1024,128,TM_SMEM>>>(pT1, 64, mw2_i, 64, 0, mb2_i, nullptr, nullptr, pQ, 64);
        k_maskgate<<<8192,256>>>(pQ, pT1, pV, mdw_i, mdb_i, pT1);    // VG -> g_T1
        // positional path
        k_dw3_gelu<<<8192,256>>>(pV, pe1_i, pK);                     // P -> g_K
        // folded attention apply + proj, added straight into X
        k_tmma<1,1,2,0><<<1024,128,TM_SMEM>>>(pT1, 64, pMC, 64, 4096, bp_i, nullptr, nullptr, pX, 64);
        k_msa_out<<<8192,256>>>(pK, pe2_i, pX);                      // X += dw3(P)
        // feed-forward: LN fused into ff1 staging; dw3+gelu fused into ff2 staging
        k_tmma<1,4,1,1><<<1024,128,TM_SMEM>>>(pX, 64, fw1_i, 256, 0, nullptr, lng_i, lnb_i, pH1, 256);
        k_tmma<4,1,2,2><<<1024,128,TM_SMEM>>>(pH1, 256, fw2_i, 64, 0, nullptr, fdw_i, nullptr, pX, 64);
    }

    k_nhwc2nchw<<<tg,256>>>(pX, out);
}

// round 10
// speedup vs baseline: 1.0361x; 1.0361x over previous
#include <cuda_runtime.h>
#include <math.h>
#include <stdint.h>

#define NPB 65536
#define NT  131072

// ---------------- scratch ----------
__device__ float g_X [NT*64];
__device__ float g_Mk[NT*64];
__device__ float g_Q [NT*64];
__device__ float g_K [NT*64];
__device__ float g_V [NT*64];
__device__ float g_T1[NT*64];
__device__ float g_H1[NT*256];
__device__ float g_H2[NT*256];
__device__ float g_GP[2*512*1152];
__device__ float g_GP2[16*2304];
__device__ float g_MC[2*64*64];

__device__ __forceinline__ float gelu_f(float u){
    return 0.5f*u*(1.f+erff(u*0.70710678118654752f));
}
__device__ __forceinline__ uint32_t tf32c(float f){
    uint32_t r; asm("cvt.rna.tf32.f32 %0, %1;" : "=r"(r) : "f"(f)); return r;
}
#define MMA_TF32(d, a, b0, b1) \
  asm volatile("mma.sync.aligned.m16n8k8.row.col.f32.tf32.tf32.f32 " \
    "{%0,%1,%2,%3},{%4,%5,%6,%7},{%8,%9},{%0,%1,%2,%3};" \
    : "+f"((d)[0]),"+f"((d)[1]),"+f"((d)[2]),"+f"((d)[3]) \
    : "r"((a)[0]),"r"((a)[1]),"r"((a)[2]),"r"((a)[3]),"r"(b0),"r"(b1))

#define XS_STRIDE 68
#define WS_STRIDE 72
#define XS_U (128*XS_STRIDE)
#define WS_U (64*WS_STRIDE)
#define TM_SMEM ((XS_U + WS_U + 64)*4)

// ---------------- tf32 tensor GEMM -----------------------------------------
// Tile 128px(M) x 64out(N), K=64/chunk. 128 threads = 4 warps.
// KC: K chunks (acc persists). NC: N chunks. MODE: 0 store,1 gelu,2 add.
// FUSE: 0 plain, 1 LayerNorm on X during staging (xa=gamma,xb=beta).
template<int KC,int NC,int MODE,int FUSE>
__global__ __launch_bounds__(128, 4) void k_tmma(
        const float* __restrict__ X, int xStride,
        const float* __restrict__ W, int wStride, int wBatchStride,
        const float* __restrict__ bias,
        const float* __restrict__ xa, const float* __restrict__ xb,
        float* __restrict__ OUT, int oStride){
    extern __shared__ uint32_t smu[];
    uint32_t* xs = smu;
    uint32_t* ws = smu + XS_U;
    float*    sb = (float*)(smu + XS_U + WS_U);
    const int t = threadIdx.x;
    const int warp = t>>5, lane = t&31;
    const int lr = lane>>2, lc = lane&3;
    const int m0 = warp*32;
    const int c4f = t&15;
    const size_t tileBase = (size_t)blockIdx.x*128;
    const float* Wb = W + (wBatchStride ? (int)(tileBase>>16)*(size_t)wBatchStride : 0);
    if(bias && t<64) sb[t] = bias[t];

    float4 g4, b4;
    if(FUSE==1){
        g4 = *(const float4*)(xa + c4f*4);
        b4 = *(const float4*)(xb + c4f*4);
    }

    float acc[64];
    const int CH = (KC>NC)?KC:NC;

    for(int c=0;c<CH;c++){
        const int kOff = (KC>1)? c*64 : 0;
        const int nOff = (NC>1)? c*64 : 0;
        if(c) __syncthreads();
        if(c==0 || KC>1){
            #pragma unroll
            for(int it=0;it<16;it++){
                int s4 = t + it*128;
                int p = s4>>4, c4 = s4&15;
                float4 v = *(const float4*)(X + (tileBase+p)*(size_t)xStride + kOff + c4*4);
                if(FUSE==1){
                    float s1 = v.x+v.y+v.z+v.w;
                    float s2 = v.x*v.x+v.y*v.y+v.z*v.z+v.w*v.w;
                    #pragma unroll
                    for(int sw=1;sw<16;sw<<=1){
                        s1 += __shfl_xor_sync(0xffffffffu, s1, sw);
                        s2 += __shfl_xor_sync(0xffffffffu, s2, sw);
                    }
                    float mu = s1*(1.f/64.f);
                    float var = fmaxf(s2*(1.f/64.f) - mu*mu, 0.f);
                    float rs = rsqrtf(var + 1e-5f);
                    v.x = (v.x-mu)*rs*g4.x + b4.x;
                    v.y = (v.y-mu)*rs*g4.y + b4.y;
                    v.z = (v.z-mu)*rs*g4.z + b4.z;
                    v.w = (v.w-mu)*rs*g4.w + b4.w;
                }
                uint32_t* xr = xs + p*XS_STRIDE + c4*4;
                xr[0]=tf32c(v.x); xr[1]=tf32c(v.y); xr[2]=tf32c(v.z); xr[3]=tf32c(v.w);
            }
        }
        #pragma unroll
        for(int it=0;it<32;it++){
            int s = t + it*128;
            int o = s&63, j = s>>6;
            ws[j*WS_STRIDE+o] = tf32c(Wb[(size_t)(kOff+j)*wStride + nOff + o]);
        }
        __syncthreads();
        if(c==0 || NC>1){
            if(bias){
                #pragma unroll
                for(int mt=0;mt<2;mt++)
                    #pragma unroll
                    for(int j=0;j<8;j++){
                        float b0 = sb[j*8 + 2*lc], b1 = sb[j*8 + 2*lc + 1];
                        acc[mt*32+j*4+0]=b0; acc[mt*32+j*4+1]=b1;
                        acc[mt*32+j*4+2]=b0; acc[mt*32+j*4+3]=b1;
                    }
            } else {
                #pragma unroll
                for(int q=0;q<64;q++) acc[q]=0.f;
            }
        }
        #pragma unroll
        for(int k0=0;k0<64;k0+=8){
            uint32_t a[2][4];
            #pragma unroll
            for(int mt=0;mt<2;mt++){
                const uint32_t* xbp = xs + (m0+mt*16+lr)*XS_STRIDE + k0 + lc;
                a[mt][0]=xbp[0]; a[mt][1]=xbp[8*XS_STRIDE];
                a[mt][2]=xbp[4]; a[mt][3]=xbp[8*XS_STRIDE+4];
            }
            #pragma unroll
            for(int j=0;j<8;j++){
                uint32_t b0 = ws[(k0+lc  )*WS_STRIDE + j*8 + lr];
                uint32_t b1 = ws[(k0+lc+4)*WS_STRIDE + j*8 + lr];
                MMA_TF32(acc +      j*4, a[0], b0, b1);
                MMA_TF32(acc + 32 + j*4, a[1], b0, b1);
            }
        }
        if(NC>1 || c==CH-1){
            #pragma unroll
            for(int mt=0;mt<2;mt++){
                #pragma unroll
                for(int j=0;j<8;j++){
                    size_t row = tileBase + m0 + mt*16 + lr;
                    int col = nOff + j*8 + 2*lc;
                    float v0=acc[mt*32+j*4], v1=acc[mt*32+j*4+1];
                    float v2=acc[mt*32+j*4+2], v3=acc[mt*32+j*4+3];
                    if(MODE==1){ v0=gelu_f(v0); v1=gelu_f(v1); v2=gelu_f(v2); v3=gelu_f(v3); }
                    float* p0 = OUT + row*(size_t)oStride + col;
                    float* p8 = p0 + 8*(size_t)oStride;
                    if(MODE==2){
                        float2 o0 = *(float2*)p0, o8 = *(float2*)p8;
                        v0+=o0.x; v1+=o0.y; v2+=o8.x; v3+=o8.y;
                    }
                    *(float2*)p0 = make_float2(v0,v1);
                    *(float2*)p8 = make_float2(v2,v3);
                }
            }
        }
    }
}

// ---------------- fused QK gemm + gram partials ----------------------------
#define QG_SMEM ((XS_U + WS_U + XS_U)*4)
__global__ __launch_bounds__(128, 2) void k_qkgram(
        const float* __restrict__ X,
        const float* __restrict__ Wq, const float* __restrict__ Wk,
        float* __restrict__ gpart){
    extern __shared__ uint32_t smu[];
    uint32_t* xs = smu;             // tf32 X, later fp32 K
    uint32_t* ws = smu + XS_U;
    float*    qT = (float*)(smu + XS_U + WS_U);  // fp32 Q
    const int t = threadIdx.x;
    const int warp = t>>5, lane = t&31;
    const int lr = lane>>2, lc = lane&3;
    const int m0 = warp*32;
    const size_t tileBase = (size_t)blockIdx.x*128;

    #pragma unroll
    for(int it=0;it<16;it++){
        int s4 = t + it*128;
        int p = s4>>4, c4 = s4&15;
        float4 v = *(const float4*)(X + (tileBase+p)*64 + c4*4);
        uint32_t* xr = xs + p*XS_STRIDE + c4*4;
        xr[0]=tf32c(v.x); xr[1]=tf32c(v.y); xr[2]=tf32c(v.z); xr[3]=tf32c(v.w);
    }

    float acc[64];
    auto stageW = [&](const float* Wm){
        #pragma unroll
        for(int it=0;it<32;it++){
            int s = t + it*128;
            int o = s&63, j = s>>6;
            ws[j*WS_STRIDE+o] = tf32c(Wm[j*64 + o]);
        }
    };
    auto runMMA = [&](){
        #pragma unroll
        for(int q=0;q<64;q++) acc[q]=0.f;
        #pragma unroll
        for(int k0=0;k0<64;k0+=8){
            uint32_t a[2][4];
            #pragma unroll
            for(int mt=0;mt<2;mt++){
                const uint32_t* xbp = xs + (m0+mt*16+lr)*XS_STRIDE + k0 + lc;
                a[mt][0]=xbp[0]; a[mt][1]=xbp[8*XS_STRIDE];
                a[mt][2]=xbp[4]; a[mt][3]=xbp[8*XS_STRIDE+4];
            }
            #pragma unroll
            for(int j=0;j<8;j++){
                uint32_t b0 = ws[(k0+lc  )*WS_STRIDE + j*8 + lr];
                uint32_t b1 = ws[(k0+lc+4)*WS_STRIDE + j*8 + lr];
                MMA_TF32(acc +      j*4, a[0], b0, b1);
                MMA_TF32(acc + 32 + j*4, a[1], b0, b1);
            }
        }
    };
    auto dump = [&](float* dst){
        #pragma unroll
        for(int mt=0;mt<2;mt++)
            #pragma unroll
            for(int j=0;j<8;j++){
                int row = m0+mt*16+lr, col = j*8+2*lc;
                dst[row*XS_STRIDE+col]   = acc[mt*32+j*4+0];
                dst[row*XS_STRIDE+col+1] = acc[mt*32+j*4+1];
                dst[(row+8)*XS_STRIDE+col]   = acc[mt*32+j*4+2];
                dst[(row+8)*XS_STRIDE+col+1] = acc[mt*32+j*4+3];
            }
    };

    stageW(Wq);
    __syncthreads();
    runMMA();
    dump(qT);
    __syncthreads();
    stageW(Wk);
    __syncthreads();
    runMMA();
    __syncthreads();
    dump((float*)xs);
    __syncthreads();

    const float* kf = (float*)xs;
    const int h = warp;
    const int db = (lane&7)*2, eb = (lane>>3)*4;
    float s00=0,s01=0,s02=0,s03=0,s10=0,s11=0,s12=0,s13=0;
    float nrm = 0.f;
    const int nc = t&63;
    const float* nf = (t<64)? qT : kf;
    #pragma unroll 4
    for(int p=0;p<128;p++){
        const float* qr = qT + p*XS_STRIDE + h*16;
        const float* kr = kf + p*XS_STRIDE + h*16;
        float k0v = kr[db], k1v = kr[db+1];
        float q0 = qr[eb], q1 = qr[eb+1], q2 = qr[eb+2], q3 = qr[eb+3];
        s00 += k0v*q0; s01 += k0v*q1; s02 += k0v*q2; s03 += k0v*q3;
        s10 += k1v*q0; s11 += k1v*q1; s12 += k1v*q2; s13 += k1v*q3;
        float nv = nf[p*XS_STRIDE + nc];
        nrm += nv*nv;
    }
    float* gp = gpart + (size_t)blockIdx.x*1152;
    float* gs = gp + h*256 + db*16 + eb;
    gs[0]=s00; gs[1]=s01; gs[2]=s02; gs[3]=s03;
    gs[16]=s10; gs[17]=s11; gs[18]=s12; gs[19]=s13;
    gp[1024+t] = nrm;
}

// ---------------- gram reduction: 16 partial slabs -------------------------
__global__ __launch_bounds__(128) void k_gred(const float* __restrict__ gpart,
        float* __restrict__ gp2){
    int j = blockIdx.x*128 + threadIdx.x;
    int b = blockIdx.y;
    int part = blockIdx.z;
    float acc = 0.f;
    const float* gp = gpart + ((size_t)b*512 + part*32)*1152 + j;
    #pragma unroll 8
    for(int tile=0;tile<32;tile++) acc += gp[(size_t)tile*1152];
    gp2[part*2304 + b*1152 + j] = acc;
}

// ---------------- attn softmax + fold into Mcomb ---------------------------
__global__ __launch_bounds__(256) void k_attn(const float* __restrict__ gp2,
        const float* __restrict__ Wp, const float* __restrict__ resc,
        float* __restrict__ Mcomb){
    __shared__ float sred[2304];
    __shared__ float sa[2048];
    int tid = threadIdx.x;
    for(int jj=tid;jj<2304;jj+=256){
        float acc=0.f;
        #pragma unroll
        for(int p=0;p<16;p++) acc += gp2[p*2304 + jj];
        sred[jj]=acc;
    }
    __syncthreads();
    if(tid<128){
        int b=tid>>6, hd=tid&63, h=hd>>4, d=hd&15;
        float nk = fmaxf(sqrtf(sred[b*1152+1088+hd]),1e-6f);
        float r = resc[h];
        float row[16]; float mx=-1e30f;
        #pragma unroll
        for(int e=0;e<16;e++){
            float nq = fmaxf(sqrtf(sred[b*1152+1024+h*16+e]),1e-6f);
            float v = sred[b*1152 + h*256 + d*16 + e] / (nk*nq) * r;
            row[e]=v; mx=fmaxf(mx,v);
        }
        float s=0.f;
        #pragma unroll
        for(int e=0;e<16;e++){ row[e]=expf(row[e]-mx); s+=row[e]; }
        float inv=1.f/s;
        #pragma unroll
        for(int e=0;e<16;e++) sa[((b*4+h)*16+d)*16+e] = row[e]*inv;
    }
    __syncthreads();
    for(int job=tid;job<8192;job+=256){
        int b=job>>12, rem=job&4095, ci=rem>>6, co=rem&63;
        int h=ci>>4, e=ci&15;
        float acc=0.f;
        #pragma unroll
        for(int d=0;d<16;d++) acc += sa[((b*4+h)*16+d)*16+e] * Wp[(h*16+d)*64+co];
        Mcomb[job]=acc;
    }
}

// ---------------- transposes ----------------
__global__ __launch_bounds__(256) void k_nchw2nhwc(const float* __restrict__ in, float* __restrict__ out){
    __shared__ float t[32][33];
    int tx = threadIdx.x & 31, ty = threadIdx.x >> 5;
    int pt = blockIdx.x, ct = blockIdx.y, b = blockIdx.z;
    const float* ip = in  + (size_t)b*64*NPB;
    float*       op = out + (size_t)b*NPB*64;
    #pragma unroll
    for(int r=0;r<4;r++){
        int c = ct*32 + ty + r*8;
        t[ty+r*8][tx] = ip[(size_t)c*NPB + (size_t)pt*32 + tx];
    }
    __syncthreads();
    #pragma unroll
    for(int r=0;r<4;r++){
        int p = pt*32 + ty + r*8;
        op[(size_t)p*64 + ct*32 + tx] = t[tx][ty+r*8];
    }
}
__global__ __launch_bounds__(256) void k_nhwc2nchw(const float* __restrict__ in, float* __restrict__ out){
    __shared__ float t[32][33];
    int tx = threadIdx.x & 31, ty = threadIdx.x >> 5;
    int pt = blockIdx.x, ct = blockIdx.y, b = blockIdx.z;
    const float* ip = in  + (size_t)b*NPB*64;
    float*       op = out + (size_t)b*64*NPB;
    #pragma unroll
    for(int r=0;r<4;r++){
        int p = pt*32 + ty + r*8;
        t[ty+r*8][tx] = ip[(size_t)p*64 + ct*32 + tx];
    }
    __syncthreads();
    #pragma unroll
    for(int r=0;r<4;r++){
        int c = ct*32 + ty + r*8;
        op[(size_t)c*NPB + (size_t)pt*32 + tx] = t[tx][ty+r*8];
    }
}

// ---------------- mask gate (float4) ---------------------------------------
__global__ __launch_bounds__(256) void k_maskgate(const float* __restrict__ T,
        const float* __restrict__ M1, const float* __restrict__ V,
        const float* __restrict__ dw, const float* __restrict__ db,
        float* __restrict__ VG){
    __shared__ float4 sdw[400];
    __shared__ float4 sdb4[16];
    int tid=threadIdx.x;
    for(int i=tid;i<400;i+=256) sdw[i]=((const float4*)dw)[i];
    if(tid<16) sdb4[tid]=((const float4*)db)[tid];
    __syncthreads();
    size_t e=(size_t)blockIdx.x*256+tid;
    int c4=(int)(e&15);
    size_t p=e>>4;
    int b=(int)(p>>16);
    int pp=(int)(p&65535);
    int y=pp>>8, x=pp&255;
    float4 conv=make_float4(0,0,0,0);
    #pragma unroll
    for(int dy=0;dy<5;dy++){
        int yy=y+dy-2; if(yy<0||yy>255) continue;
        #pragma unroll
        for(int dx=0;dx<5;dx++){
            int xx=x+dx-2; if(xx<0||xx>255) continue;
            float4 tv = *(const float4*)(T + (((((size_t)b<<16)+(yy<<8)+xx)<<6)+c4*4));
            float4 wv = sdw[(dy*5+dx)*16+c4];
            conv.x+=tv.x*wv.x; conv.y+=tv.y*wv.y; conv.z+=tv.z*wv.z; conv.w+=tv.w*wv.w;
        }
    }
    float4 bb=sdb4[c4];
    float4 m1=((const float4*)M1)[e];
    float4 vv=((const float4*)V)[e];
    float4 r;
    r.x = vv.x*m1.x*(1.f+1.f/(1.f+expf(-(conv.x+bb.x))));
    r.y = vv.y*m1.y*(1.f+1.f/(1.f+expf(-(conv.y+bb.y))));
    r.z = vv.z*m1.z*(1.f+1.f/(1.f+expf(-(conv.z+bb.z))));
    r.w = vv.w*m1.w*(1.f+1.f/(1.f+expf(-(conv.w+bb.w))));
    ((float4*)VG)[e]=r;
}

// ---------------- depthwise 3x3 + GELU (float4, C=1<<cbits) ----------------
__global__ __launch_bounds__(256) void k_dw3_gelu(const float* __restrict__ in,
        const float* __restrict__ dw, float* __restrict__ out, int cbits){
    __shared__ float4 sdw[576];
    int tid=threadIdx.x;
    int C4=1<<(cbits-2);
    for(int i=tid;i<9*C4;i+=256) sdw[i]=((const float4*)dw)[i];
    __syncthreads();
    size_t e=(size_t)blockIdx.x*256+tid;
    int c4=(int)(e&(C4-1));
    size_t p=e>>(cbits-2);
    int b=(int)(p>>16), pp=(int)(p&65535), y=pp>>8, x=pp&255;
    float4 conv=make_float4(0,0,0,0);
    #pragma unroll
    for(int dy=0;dy<3;dy++){
        int yy=y+dy-1; if(yy<0||yy>255) continue;
        #pragma unroll
        for(int dx=0;dx<3;dx++){
            int xx=x+dx-1; if(xx<0||xx>255) continue;
            float4 tv = *(const float4*)(in + ((((((size_t)b<<16)+(yy<<8)+xx))<<cbits)+c4*4));
            float4 wv = sdw[(dy*3+dx)*C4+c4];
            conv.x+=tv.x*wv.x; conv.y+=tv.y*wv.y; conv.z+=tv.z*wv.z; conv.w+=tv.w*wv.w;
        }
    }
    float4 r=make_float4(gelu_f(conv.x),gelu_f(conv.y),gelu_f(conv.z),gelu_f(conv.w));
    ((float4*)out)[e]=r;
}

// ---------------- msa epilogue: X += dw3(P, pe2) (float4) ------------------
__global__ __launch_bounds__(256) void k_msa_out(
        const float* __restrict__ P, const float* __restrict__ pe2,
        float* __restrict__ X){
    __shared__ float4 sdw[144];
    int tid=threadIdx.x;
    if(tid<144) sdw[tid]=((const float4*)pe2)[tid];
    __syncthreads();
    size_t e=(size_t)blockIdx.x*256+tid;
    int c4=(int)(e&15);
    size_t p=e>>4;
    int b=(int)(p>>16), pp=(int)(p&65535), y=pp>>8, x=pp&255;
    float4 conv=make_float4(0,0,0,0);
    #pragma unroll
    for(int dy=0;dy<3;dy++){
        int yy=y+dy-1; if(yy<0||yy>255) continue;
        #pragma unroll
        for(int dx=0;dx<3;dx++){
            int xx=x+dx-1; if(xx<0||xx>255) continue;
            float4 tv = *(const float4*)(P + (((((size_t)b<<16)+(yy<<8)+xx)<<6)+c4*4));
            float4 wv = sdw[(dy*3+dx)*16+c4];
            conv.x+=tv.x*wv.x; conv.y+=tv.y*wv.y; conv.z+=tv.z*wv.z; conv.w+=tv.w*wv.w;
        }
    }
    float4 xv=((float4*)X)[e];
    xv.x+=conv.x; xv.y+=conv.y; xv.z+=conv.z; xv.w+=conv.w;
    ((float4*)X)[e]=xv;
}

// ---------------- host -----------------------------------------------------
extern "C" void kernel_launch(void* const* d_in, const int* in_sizes, int n_in,
                              void* d_out, int out_size){
    const float* x    = (const float*)d_in[0];
    const float* mask = (const float*)d_in[1];
    const float* Wq   = (const float*)d_in[2];
    const float* Wk   = (const float*)d_in[3];
    const float* Wv   = (const float*)d_in[4];
    const float* resc = (const float*)d_in[5];
    const float* Wp   = (const float*)d_in[6];
    const float* bp   = (const float*)d_in[7];
    const float* pe1  = (const float*)d_in[8];
    const float* pe2  = (const float*)d_in[9];
    const float* mw1  = (const float*)d_in[10];
    const float* mb1  = (const float*)d_in[11];
    const float* mw2  = (const float*)d_in[12];
    const float* mb2  = (const float*)d_in[13];
    const float* mdw  = (const float*)d_in[14];
    const float* mdb  = (const float*)d_in[15];
    const float* lng  = (const float*)d_in[16];
    const float* lnb  = (const float*)d_in[17];
    const float* fw1  = (const float*)d_in[18];
    const float* fdw  = (const float*)d_in[19];
    const float* fw2  = (const float*)d_in[20];
    float* out = (float*)d_out;

    float *pX,*pM,*pQ,*pK,*pV,*pT1,*pH1,*pH2,*pGP,*pGP2,*pMC;
    cudaGetSymbolAddress((void**)&pX,  g_X);
    cudaGetSymbolAddress((void**)&pM,  g_Mk);
    cudaGetSymbolAddress((void**)&pQ,  g_Q);
    cudaGetSymbolAddress((void**)&pK,  g_K);
    cudaGetSymbolAddress((void**)&pV,  g_V);
    cudaGetSymbolAddress((void**)&pT1, g_T1);
    cudaGetSymbolAddress((void**)&pH1, g_H1);
    cudaGetSymbolAddress((void**)&pH2, g_H2);
    cudaGetSymbolAddress((void**)&pGP, g_GP);
    cudaGetSymbolAddress((void**)&pGP2,g_GP2);
    cudaGetSymbolAddress((void**)&pMC, g_MC);

    cudaFuncSetAttribute(k_tmma<1,1,0,0>, cudaFuncAttributeMaxDynamicSharedMemorySize, TM_SMEM);
    cudaFuncSetAttribute(k_tmma<1,1,2,0>, cudaFuncAttributeMaxDynamicSharedMemorySize, TM_SMEM);
    cudaFuncSetAttribute(k_tmma<1,4,1,1>, cudaFuncAttributeMaxDynamicSharedMemorySize, TM_SMEM);
    cudaFuncSetAttribute(k_tmma<4,1,2,0>, cudaFuncAttributeMaxDynamicSharedMemorySize, TM_SMEM);
    cudaFuncSetAttribute(k_qkgram, cudaFuncAttributeMaxDynamicSharedMemorySize, QG_SMEM);

    dim3 tg(2048,2,2);
    k_nchw2nhwc<<<tg,256>>>(x,    pX);
    k_nchw2nhwc<<<tg,256>>>(mask, pM);

    for(int i=0;i<3;i++){
        const float* Wq_i  = Wq  + i*4096;
        const float* Wk_i  = Wk  + i*4096;
        const float* Wv_i  = Wv  + i*4096;
        const float* Wp_i  = Wp  + i*4096;
        const float* mw1_i = mw1 + i*4096;
        const float* mw2_i = mw2 + i*4096;
        const float* bp_i  = bp  + i*64;
        const float* mb1_i = mb1 + i*64;
        const float* mb2_i = mb2 + i*64;
        const float* mdb_i = mdb + i*64;
        const float* lng_i = lng + i*64;
        const float* lnb_i = lnb + i*64;
        const float* pe1_i = pe1 + i*576;
        const float* pe2_i = pe2 + i*576;
        const float* mdw_i = mdw + i*1600;
        const float* rs_i  = resc+ i*4;
        const float* fw1_i = fw1 + i*64*256;
        const float* fdw_i = fdw + i*9*256;
        const float* fw2_i = fw2 + i*256*64;

        // fused attention stats
        k_qkgram<<<1024,128,QG_SMEM>>>(pX, Wq_i, Wk_i, pGP);
        k_gred<<<dim3(9,2,16),128>>>(pGP, pGP2);
        k_attn<<<1,256>>>(pGP2, Wp_i, rs_i, pMC);
        // v + mask gate
        k_tmma<1,1,0,0><<<1024,128,TM_SMEM>>>(pX, 64, Wv_i, 64, 0, nullptr, nullptr, nullptr, pV, 64);
        k_tmma<1,1,0,0><<<1024,128,TM_SMEM>>>(pM, 64, mw1_i, 64, 0, mb1_i, nullptr, nullptr, pT1, 64);
        k_tmma<1,1,0,0><<<1024,128,TM_SMEM>>>(pT1, 64, mw2_i, 64, 0, mb2_i, nullptr, nullptr, pQ, 64);
        k_maskgate<<<8192,256>>>(pQ, pT1, pV, mdw_i, mdb_i, pT1);    // VG -> g_T1
        // positional path
        k_dw3_gelu<<<8192,256>>>(pV, pe1_i, pK, 6);                  // P -> g_K
        // folded attention apply + proj, added straight into X
        k_tmma<1,1,2,0><<<1024,128,TM_SMEM>>>(pT1, 64, pMC, 64, 4096, bp_i, nullptr, nullptr, pX, 64);
        k_msa_out<<<8192,256>>>(pK, pe2_i, pX);                      // X += dw3(P)
        // feed-forward: LN fused into ff1 staging
        k_tmma<1,4,1,1><<<1024,128,TM_SMEM>>>(pX, 64, fw1_i, 256, 0, nullptr, lng_i, lnb_i, pH1, 256);
        k_dw3_gelu<<<32768,256>>>(pH1, fdw_i, pH2, 8);
        k_tmma<4,1,2,0><<<1024,128,TM_SMEM>>>(pH2, 256, fw2_i, 64, 0, nullptr, nullptr, nullptr, pX, 64);
    }

    k_nhwc2nchw<<<tg,256>>>(pX, out);
}

// round 11
// speedup vs baseline: 1.2484x; 1.2050x over previous
#include <cuda_runtime.h>
#include <math.h>
#include <stdint.h>

#define NPB 65536
#define NT  131072

// ---------------- scratch ----------
__device__ float g_X [NT*64];
__device__ float g_Mk[NT*64];
__device__ float g_Q [NT*64];
__device__ float g_K [NT*64];
__device__ float g_V [NT*64];
__device__ float g_T1[NT*64];
__device__ float g_H1[NT*256];
__device__ float g_H2[NT*256];
__device__ float g_GP[2*128*1152];
__device__ float g_MC[2*64*64];

__device__ __forceinline__ float gelu_f(float u){
    return 0.5f*u*(1.f+erff(u*0.70710678118654752f));
}
__device__ __forceinline__ uint32_t tf32c(float f){
    uint32_t r; asm("cvt.rna.tf32.f32 %0, %1;" : "=r"(r) : "f"(f)); return r;
}
#define MMA_TF32(d, a, b0, b1) \
  asm volatile("mma.sync.aligned.m16n8k8.row.col.f32.tf32.tf32.f32 " \
    "{%0,%1,%2,%3},{%4,%5,%6,%7},{%8,%9},{%0,%1,%2,%3};" \
    : "+f"((d)[0]),"+f"((d)[1]),"+f"((d)[2]),"+f"((d)[3]) \
    : "r"((a)[0]),"r"((a)[1]),"r"((a)[2]),"r"((a)[3]),"r"(b0),"r"(b1))

#define XS_STRIDE 68
#define WS_STRIDE 72
#define XS_U (128*XS_STRIDE)
#define WS_U (64*WS_STRIDE)
#define TM_SMEM ((XS_U + WS_U + 64)*4)

// ---------------- tf32 tensor GEMM -----------------------------------------
// Tile 128px(M) x 64out(N), K=64/chunk. 128 threads = 4 warps.
// KC: K chunks. NC: N chunks. MODE: 0 store,1 gelu,2 add.
// FUSE: 0 plain, 1 LayerNorm on X during staging (xa=gamma,xb=beta).
template<int KC,int NC,int MODE,int FUSE>
__global__ __launch_bounds__(128, 4) void k_tmma(
        const float* __restrict__ X, int xStride,
        const float* __restrict__ W, int wStride, int wBatchStride,
        const float* __restrict__ bias,
        const float* __restrict__ xa, const float* __restrict__ xb,
        float* __restrict__ OUT, int oStride){
    extern __shared__ uint32_t smu[];
    uint32_t* xs = smu;
    uint32_t* ws = smu + XS_U;
    float*    sb = (float*)(smu + XS_U + WS_U);
    const int t = threadIdx.x;
    const int warp = t>>5, lane = t&31;
    const int lr = lane>>2, lc = lane&3;
    const int m0 = warp*32;
    const int c4f = t&15;
    const size_t tileBase = (size_t)blockIdx.x*128;
    const float* Wb = W + (wBatchStride ? (int)(tileBase>>16)*(size_t)wBatchStride : 0);
    if(bias && t<64) sb[t] = bias[t];

    float4 g4, b4;
    if(FUSE==1){
        g4 = *(const float4*)(xa + c4f*4);
        b4 = *(const float4*)(xb + c4f*4);
    }

    float acc[64];
    const int CH = (KC>NC)?KC:NC;

    for(int c=0;c<CH;c++){
        const int kOff = (KC>1)? c*64 : 0;
        const int nOff = (NC>1)? c*64 : 0;
        if(c) __syncthreads();
        if(c==0 || KC>1){
            #pragma unroll
            for(int it=0;it<16;it++){
                int s4 = t + it*128;
                int p = s4>>4, c4 = s4&15;
                float4 v = *(const float4*)(X + (tileBase+p)*(size_t)xStride + kOff + c4*4);
                if(FUSE==1){
                    float s1 = v.x+v.y+v.z+v.w;
                    float s2 = v.x*v.x+v.y*v.y+v.z*v.z+v.w*v.w;
                    #pragma unroll
                    for(int sw=1;sw<16;sw<<=1){
                        s1 += __shfl_xor_sync(0xffffffffu, s1, sw);
                        s2 += __shfl_xor_sync(0xffffffffu, s2, sw);
                    }
                    float mu = s1*(1.f/64.f);
                    float var = fmaxf(s2*(1.f/64.f) - mu*mu, 0.f);
                    float rs = rsqrtf(var + 1e-5f);
                    v.x = (v.x-mu)*rs*g4.x + b4.x;
                    v.y = (v.y-mu)*rs*g4.y + b4.y;
                    v.z = (v.z-mu)*rs*g4.z + b4.z;
                    v.w = (v.w-mu)*rs*g4.w + b4.w;
                }
                uint32_t* xr = xs + p*XS_STRIDE + c4*4;
                xr[0]=tf32c(v.x); xr[1]=tf32c(v.y); xr[2]=tf32c(v.z); xr[3]=tf32c(v.w);
            }
        }
        #pragma unroll
        for(int it=0;it<32;it++){
            int s = t + it*128;
            int o = s&63, j = s>>6;
            ws[j*WS_STRIDE+o] = tf32c(Wb[(size_t)(kOff+j)*wStride + nOff + o]);
        }
        __syncthreads();
        if(c==0 || NC>1){
            if(bias){
                #pragma unroll
                for(int mt=0;mt<2;mt++)
                    #pragma unroll
                    for(int j=0;j<8;j++){
                        float b0 = sb[j*8 + 2*lc], b1 = sb[j*8 + 2*lc + 1];
                        acc[mt*32+j*4+0]=b0; acc[mt*32+j*4+1]=b1;
                        acc[mt*32+j*4+2]=b0; acc[mt*32+j*4+3]=b1;
                    }
            } else {
                #pragma unroll
                for(int q=0;q<64;q++) acc[q]=0.f;
            }
        }
        #pragma unroll
        for(int k0=0;k0<64;k0+=8){
            uint32_t a[2][4];
            #pragma unroll
            for(int mt=0;mt<2;mt++){
                const uint32_t* xbp = xs + (m0+mt*16+lr)*XS_STRIDE + k0 + lc;
                a[mt][0]=xbp[0]; a[mt][1]=xbp[8*XS_STRIDE];
                a[mt][2]=xbp[4]; a[mt][3]=xbp[8*XS_STRIDE+4];
            }
            #pragma unroll
            for(int j=0;j<8;j++){
                uint32_t b0 = ws[(k0+lc  )*WS_STRIDE + j*8 + lr];
                uint32_t b1 = ws[(k0+lc+4)*WS_STRIDE + j*8 + lr];
                MMA_TF32(acc +      j*4, a[0], b0, b1);
                MMA_TF32(acc + 32 + j*4, a[1], b0, b1);
            }
        }
        if(NC>1 || c==CH-1){
            #pragma unroll
            for(int mt=0;mt<2;mt++){
                #pragma unroll
                for(int j=0;j<8;j++){
                    size_t row = tileBase + m0 + mt*16 + lr;
                    int col = nOff + j*8 + 2*lc;
                    float v0=acc[mt*32+j*4], v1=acc[mt*32+j*4+1];
                    float v2=acc[mt*32+j*4+2], v3=acc[mt*32+j*4+3];
                    if(MODE==1){ v0=gelu_f(v0); v1=gelu_f(v1); v2=gelu_f(v2); v3=gelu_f(v3); }
                    float* p0 = OUT + row*(size_t)oStride + col;
                    float* p8 = p0 + 8*(size_t)oStride;
                    if(MODE==2){
                        float2 o0 = *(float2*)p0, o8 = *(float2*)p8;
                        v0+=o0.x; v1+=o0.y; v2+=o8.x; v3+=o8.y;
                    }
                    *(float2*)p0 = make_float2(v0,v1);
                    *(float2*)p8 = make_float2(v2,v3);
                }
            }
        }
    }
}

// ---------------- fused QKV gemm: stage X once, 3 weight mats --------------
__global__ __launch_bounds__(128, 4) void k_qkv(
        const float* __restrict__ X,
        const float* __restrict__ Wq, const float* __restrict__ Wk,
        const float* __restrict__ Wv,
        float* __restrict__ Qo, float* __restrict__ Ko, float* __restrict__ Vo){
    extern __shared__ uint32_t smu[];
    uint32_t* xs = smu;
    uint32_t* ws = smu + XS_U;
    const int t = threadIdx.x;
    const int warp = t>>5, lane = t&31;
    const int lr = lane>>2, lc = lane&3;
    const int m0 = warp*32;
    const size_t tileBase = (size_t)blockIdx.x*128;

    #pragma unroll
    for(int it=0;it<16;it++){
        int s4 = t + it*128;
        int p = s4>>4, c4 = s4&15;
        float4 v = *(const float4*)(X + (tileBase+p)*64 + c4*4);
        uint32_t* xr = xs + p*XS_STRIDE + c4*4;
        xr[0]=tf32c(v.x); xr[1]=tf32c(v.y); xr[2]=tf32c(v.z); xr[3]=tf32c(v.w);
    }

    const float* Ws[3] = {Wq, Wk, Wv};
    float* Os[3] = {Qo, Ko, Vo};
    float acc[64];
    #pragma unroll 1
    for(int m=0;m<3;m++){
        if(m) __syncthreads();
        const float* Wm = Ws[m];
        #pragma unroll
        for(int it=0;it<32;it++){
            int s = t + it*128;
            int o = s&63, j = s>>6;
            ws[j*WS_STRIDE+o] = tf32c(Wm[j*64 + o]);
        }
        __syncthreads();
        #pragma unroll
        for(int q=0;q<64;q++) acc[q]=0.f;
        #pragma unroll
        for(int k0=0;k0<64;k0+=8){
            uint32_t a[2][4];
            #pragma unroll
            for(int mt=0;mt<2;mt++){
                const uint32_t* xbp = xs + (m0+mt*16+lr)*XS_STRIDE + k0 + lc;
                a[mt][0]=xbp[0]; a[mt][1]=xbp[8*XS_STRIDE];
                a[mt][2]=xbp[4]; a[mt][3]=xbp[8*XS_STRIDE+4];
            }
            #pragma unroll
            for(int j=0;j<8;j++){
                uint32_t b0 = ws[(k0+lc  )*WS_STRIDE + j*8 + lr];
                uint32_t b1 = ws[(k0+lc+4)*WS_STRIDE + j*8 + lr];
                MMA_TF32(acc +      j*4, a[0], b0, b1);
                MMA_TF32(acc + 32 + j*4, a[1], b0, b1);
            }
        }
        float* O = Os[m];
        #pragma unroll
        for(int mt=0;mt<2;mt++){
            #pragma unroll
            for(int j=0;j<8;j++){
                size_t row = tileBase + m0 + mt*16 + lr;
                int col = j*8 + 2*lc;
                float* p0 = O + row*64 + col;
                float* p8 = p0 + 8*64;
                *(float2*)p0 = make_float2(acc[mt*32+j*4+0], acc[mt*32+j*4+1]);
                *(float2*)p8 = make_float2(acc[mt*32+j*4+2], acc[mt*32+j*4+3]);
            }
        }
    }
}

// ---------------- gram partials (R7 known-good) ----------------------------
__global__ __launch_bounds__(256) void k_gram(const float* __restrict__ Q,
        const float* __restrict__ K, float* __restrict__ gpart){
    __shared__ float sq[4096], sk[4096];
    __shared__ float pS[1024];
    __shared__ float pn[128];
    int tid = threadIdx.x;
    int b = blockIdx.y;
    for(int i=tid;i<1024;i+=256) pS[i]=0.f;
    if(tid<128) pn[tid]=0.f;
    for(int t=0;t<8;t++){
        size_t base = ((size_t)b*NPB + (size_t)blockIdx.x*512 + t*64)*64;
        __syncthreads();
        for(int i=tid;i<4096;i+=256){ sq[i]=Q[base+i]; sk[i]=K[base+i]; }
        __syncthreads();
        #pragma unroll
        for(int jj=0;jj<4;jj++){
            int job = tid + jj*256;
            int h=job>>8, d=(job>>4)&15, e=job&15;
            int ck=h*16+d, cq=h*16+e;
            float acc=0.f;
            #pragma unroll 8
            for(int p=0;p<64;p++) acc += sk[p*64+ck]*sq[p*64+cq];
            pS[job]+=acc;
        }
        if(tid<128){
            int c=tid&63;
            const float* s = (tid<64)? sq : sk;
            float acc=0.f;
            #pragma unroll 8
            for(int p=0;p<64;p++){ float v=s[p*64+c]; acc+=v*v; }
            pn[tid]+=acc;
        }
    }
    __syncthreads();
    float* gp = gpart + ((size_t)b*128 + blockIdx.x)*1152;
    for(int i=tid;i<1024;i+=256) gp[i]=pS[i];
    if(tid<128) gp[1024+tid]=pn[tid];
}

// ---------------- attn softmax + fold into Mcomb ---------------------------
__global__ __launch_bounds__(256) void k_attn(const float* __restrict__ gpart,
        const float* __restrict__ Wp, const float* __restrict__ resc,
        float* __restrict__ Mcomb){
    __shared__ float sred[2304];
    __shared__ float sa[2048];
    int tid = threadIdx.x;
    for(int jj=tid;jj<2304;jj+=256){
        int b=jj/1152, j=jj-b*1152;
        float acc=0.f;
        for(int blk=0;blk<128;blk++) acc += gpart[((size_t)b*128+blk)*1152 + j];
        sred[jj]=acc;
    }
    __syncthreads();
    if(tid<128){
        int b=tid>>6, hd=tid&63, h=hd>>4, d=hd&15;
        float nk = fmaxf(sqrtf(sred[b*1152+1088+hd]),1e-6f);
        float r = resc[h];
        float row[16]; float mx=-1e30f;
        #pragma unroll
        for(int e=0;e<16;e++){
            float nq = fmaxf(sqrtf(sred[b*1152+1024+h*16+e]),1e-6f);
            float v = sred[b*1152 + h*256 + d*16 + e] / (nk*nq) * r;
            row[e]=v; mx=fmaxf(mx,v);
        }
        float s=0.f;
        #pragma unroll
        for(int e=0;e<16;e++){ row[e]=expf(row[e]-mx); s+=row[e]; }
        float inv=1.f/s;
        #pragma unroll
        for(int e=0;e<16;e++) sa[((b*4+h)*16+d)*16+e] = row[e]*inv;
    }
    __syncthreads();
    for(int job=tid;job<8192;job+=256){
        int b=job>>12, rem=job&4095, ci=rem>>6, co=rem&63;
        int h=ci>>4, e=ci&15;
        float acc=0.f;
        #pragma unroll
        for(int d=0;d<16;d++) acc += sa[((b*4+h)*16+d)*16+e] * Wp[(h*16+d)*64+co];
        Mcomb[job]=acc;
    }
}

// ---------------- transposes ----------------
__global__ __launch_bounds__(256) void k_nchw2nhwc(const float* __restrict__ in, float* __restrict__ out){
    __shared__ float t[32][33];
    int tx = threadIdx.x & 31, ty = threadIdx.x >> 5;
    int pt = blockIdx.x, ct = blockIdx.y, b = blockIdx.z;
    const float* ip = in  + (size_t)b*64*NPB;
    float*       op = out + (size_t)b*NPB*64;
    #pragma unroll
    for(int r=0;r<4;r++){
        int c = ct*32 + ty + r*8;
        t[ty+r*8][tx] = ip[(size_t)c*NPB + (size_t)pt*32 + tx];
    }
    __syncthreads();
    #pragma unroll
    for(int r=0;r<4;r++){
        int p = pt*32 + ty + r*8;
        op[(size_t)p*64 + ct*32 + tx] = t[tx][ty+r*8];
    }
}
__global__ __launch_bounds__(256) void k_nhwc2nchw(const float* __restrict__ in, float* __restrict__ out){
    __shared__ float t[32][33];
    int tx = threadIdx.x & 31, ty = threadIdx.x >> 5;
    int pt = blockIdx.x, ct = blockIdx.y, b = blockIdx.z;
    const float* ip = in  + (size_t)b*NPB*64;
    float*       op = out + (size_t)b*64*NPB;
    #pragma unroll
    for(int r=0;r<4;r++){
        int p = pt*32 + ty + r*8;
        t[ty+r*8][tx] = ip[(size_t)p*64 + ct*32 + tx];
    }
    __syncthreads();
    #pragma unroll
    for(int r=0;r<4;r++){
        int c = ct*32 + ty + r*8;
        op[(size_t)c*NPB + (size_t)pt*32 + tx] = t[tx][ty+r*8];
    }
}

// ---------------- mask gate (float4) ---------------------------------------
__global__ __launch_bounds__(256) void k_maskgate(const float* __restrict__ T,
        const float* __restrict__ M1, const float* __restrict__ V,
        const float* __restrict__ dw, const float* __restrict__ db,
        float* __restrict__ VG){
    __shared__ float4 sdw[400];
    __shared__ float4 sdb4[16];
    int tid=threadIdx.x;
    for(int i=tid;i<400;i+=256) sdw[i]=((const float4*)dw)[i];
    if(tid<16) sdb4[tid]=((const float4*)db)[tid];
    __syncthreads();
    size_t e=(size_t)blockIdx.x*256+tid;
    int c4=(int)(e&15);
    size_t p=e>>4;
    int b=(int)(p>>16);
    int pp=(int)(p&65535);
    int y=pp>>8, x=pp&255;
    float4 conv=make_float4(0,0,0,0);
    #pragma unroll
    for(int dy=0;dy<5;dy++){
        int yy=y+dy-2; if(yy<0||yy>255) continue;
        #pragma unroll
        for(int dx=0;dx<5;dx++){
            int xx=x+dx-2; if(xx<0||xx>255) continue;
            float4 tv = *(const float4*)(T + (((((size_t)b<<16)+(yy<<8)+xx)<<6)+c4*4));
            float4 wv = sdw[(dy*5+dx)*16+c4];
            conv.x+=tv.x*wv.x; conv.y+=tv.y*wv.y; conv.z+=tv.z*wv.z; conv.w+=tv.w*wv.w;
        }
    }
    float4 bb=sdb4[c4];
    float4 m1=((const float4*)M1)[e];
    float4 vv=((const float4*)V)[e];
    float4 r;
    r.x = vv.x*m1.x*(1.f+1.f/(1.f+expf(-(conv.x+bb.x))));
    r.y = vv.y*m1.y*(1.f+1.f/(1.f+expf(-(conv.y+bb.y))));
    r.z = vv.z*m1.z*(1.f+1.f/(1.f+expf(-(conv.z+bb.z))));
    r.w = vv.w*m1.w*(1.f+1.f/(1.f+expf(-(conv.w+bb.w))));
    ((float4*)VG)[e]=r;
}

// ---------------- depthwise 3x3 + GELU (float4, C=1<<cbits) ----------------
__global__ __launch_bounds__(256) void k_dw3_gelu(const float* __restrict__ in,
        const float* __restrict__ dw, float* __restrict__ out, int cbits){
    __shared__ float4 sdw[576];
    int tid=threadIdx.x;
    int C4=1<<(cbits-2);
    for(int i=tid;i<9*C4;i+=256) sdw[i]=((const float4*)dw)[i];
    __syncthreads();
    size_t e=(size_t)blockIdx.x*256+tid;
    int c4=(int)(e&(C4-1));
    size_t p=e>>(cbits-2);
    int b=(int)(p>>16), pp=(int)(p&65535), y=pp>>8, x=pp&255;
    float4 conv=make_float4(0,0,0,0);
    #pragma unroll
    for(int dy=0;dy<3;dy++){
        int yy=y+dy-1; if(yy<0||yy>255) continue;
        #pragma unroll
        for(int dx=0;dx<3;dx++){
            int xx=x+dx-1; if(xx<0||xx>255) continue;
            float4 tv = *(const float4*)(in + ((((((size_t)b<<16)+(yy<<8)+xx))<<cbits)+c4*4));
            float4 wv = sdw[(dy*3+dx)*C4+c4];
            conv.x+=tv.x*wv.x; conv.y+=tv.y*wv.y; conv.z+=tv.z*wv.z; conv.w+=tv.w*wv.w;
        }
    }
    float4 r=make_float4(gelu_f(conv.x),gelu_f(conv.y),gelu_f(conv.z),gelu_f(conv.w));
    ((float4*)out)[e]=r;
}

// ---------------- msa epilogue: X += dw3(P, pe2) (float4) ------------------
__global__ __launch_bounds__(256) void k_msa_out(
        const float* __restrict__ P, const float* __restrict__ pe2,
        float* __restrict__ X){
    __shared__ float4 sdw[144];
    int tid=threadIdx.x;
    if(tid<144) sdw[tid]=((const float4*)pe2)[tid];
    __syncthreads();
    size_t e=(size_t)blockIdx.x*256+tid;
    int c4=(int)(e&15);
    size_t p=e>>4;
    int b=(int)(p>>16), pp=(int)(p&65535), y=pp>>8, x=pp&255;
    float4 conv=make_float4(0,0,0,0);
    #pragma unroll
    for(int dy=0;dy<3;dy++){
        int yy=y+dy-1; if(yy<0||yy>255) continue;
        #pragma unroll
        for(int dx=0;dx<3;dx++){
            int xx=x+dx-1; if(xx<0||xx>255) continue;
            float4 tv = *(const float4*)(P + (((((size_t)b<<16)+(yy<<8)+xx)<<6)+c4*4));
            float4 wv = sdw[(dy*3+dx)*16+c4];
            conv.x+=tv.x*wv.x; conv.y+=tv.y*wv.y; conv.z+=tv.z*wv.z; conv.w+=tv.w*wv.w;
        }
    }
    float4 xv=((float4*)X)[e];
    xv.x+=conv.x; xv.y+=conv.y; xv.z+=conv.z; xv.w+=conv.w;
    ((float4*)X)[e]=xv;
}

// ---------------- host -----------------------------------------------------
extern "C" void kernel_launch(void* const* d_in, const int* in_sizes, int n_in,
                              void* d_out, int out_size){
    const float* x    = (const float*)d_in[0];
    const float* mask = (const float*)d_in[1];
    const float* Wq   = (const float*)d_in[2];
    const float* Wk   = (const float*)d_in[3];
    const float* Wv   = (const float*)d_in[4];
    const float* resc = (const float*)d_in[5];
    const float* Wp   = (const float*)d_in[6];
    const float* bp   = (const float*)d_in[7];
    const float* pe1  = (const float*)d_in[8];
    const float* pe2  = (const float*)d_in[9];
    const float* mw1  = (const float*)d_in[10];
    const float* mb1  = (const float*)d_in[11];
    const float* mw2  = (const float*)d_in[12];
    const float* mb2  = (const float*)d_in[13];
    const float* mdw  = (const float*)d_in[14];
    const float* mdb  = (const float*)d_in[15];
    const float* lng  = (const float*)d_in[16];
    const float* lnb  = (const float*)d_in[17];
    const float* fw1  = (const float*)d_in[18];
    const float* fdw  = (const float*)d_in[19];
    const float* fw2  = (const float*)d_in[20];
    float* out = (float*)d_out;

    float *pX,*pM,*pQ,*pK,*pV,*pT1,*pH1,*pH2,*pGP,*pMC;
    cudaGetSymbolAddress((void**)&pX,  g_X);
    cudaGetSymbolAddress((void**)&pM,  g_Mk);
    cudaGetSymbolAddress((void**)&pQ,  g_Q);
    cudaGetSymbolAddress((void**)&pK,  g_K);
    cudaGetSymbolAddress((void**)&pV,  g_V);
    cudaGetSymbolAddress((void**)&pT1, g_T1);
    cudaGetSymbolAddress((void**)&pH1, g_H1);
    cudaGetSymbolAddress((void**)&pH2, g_H2);
    cudaGetSymbolAddress((void**)&pGP, g_GP);
    cudaGetSymbolAddress((void**)&pMC, g_MC);

    cudaFuncSetAttribute(k_tmma<1,1,0,0>, cudaFuncAttributeMaxDynamicSharedMemorySize, TM_SMEM);
    cudaFuncSetAttribute(k_tmma<1,1,2,0>, cudaFuncAttributeMaxDynamicSharedMemorySize, TM_SMEM);
    cudaFuncSetAttribute(k_tmma<1,4,1,1>, cudaFuncAttributeMaxDynamicSharedMemorySize, TM_SMEM);
    cudaFuncSetAttribute(k_tmma<4,1,2,0>, cudaFuncAttributeMaxDynamicSharedMemorySize, TM_SMEM);
    cudaFuncSetAttribute(k_qkv, cudaFuncAttributeMaxDynamicSharedMemorySize, TM_SMEM);

    dim3 tg(2048,2,2);
    k_nchw2nhwc<<<tg,256>>>(x,    pX);
    k_nchw2nhwc<<<tg,256>>>(mask, pM);

    for(int i=0;i<3;i++){
        const float* Wq_i  = Wq  + i*4096;
        const float* Wk_i  = Wk  + i*4096;
        const float* Wv_i  = Wv  + i*4096;
        const float* Wp_i  = Wp  + i*4096;
        const float* mw1_i = mw1 + i*4096;
        const float* mw2_i = mw2 + i*4096;
        const float* bp_i  = bp  + i*64;
        const float* mb1_i = mb1 + i*64;
        const float* mb2_i = mb2 + i*64;
        const float* mdb_i = mdb + i*64;
        const float* lng_i = lng + i*64;
        const float* lnb_i = lnb + i*64;
        const float* pe1_i = pe1 + i*576;
        const float* pe2_i = pe2 + i*576;
        const float* mdw_i = mdw + i*1600;
        const float* rs_i  = resc+ i*4;
        const float* fw1_i = fw1 + i*64*256;
        const float* fdw_i = fdw + i*9*256;
        const float* fw2_i = fw2 + i*256*64;

        // fused QKV projection (X staged once)
        k_qkv<<<1024,128,TM_SMEM>>>(pX, Wq_i, Wk_i, Wv_i, pQ, pK, pV);
        k_gram<<<dim3(128,2),256>>>(pQ, pK, pGP);
        k_attn<<<1,256>>>(pGP, Wp_i, rs_i, pMC);
        // mask path
        k_tmma<1,1,0,0><<<1024,128,TM_SMEM>>>(pM, 64, mw1_i, 64, 0, mb1_i, nullptr, nullptr, pT1, 64);
        k_tmma<1,1,0,0><<<1024,128,TM_SMEM>>>(pT1, 64, mw2_i, 64, 0, mb2_i, nullptr, nullptr, pQ, 64); // Q free after gram
        k_maskgate<<<8192,256>>>(pQ, pT1, pV, mdw_i, mdb_i, pT1);    // VG -> g_T1
        // positional path
        k_dw3_gelu<<<8192,256>>>(pV, pe1_i, pK, 6);                  // P -> g_K (K free after gram)
        // folded attention apply + proj, added straight into X
        k_tmma<1,1,2,0><<<1024,128,TM_SMEM>>>(pT1, 64, pMC, 64, 4096, bp_i, nullptr, nullptr, pX, 64);
        k_msa_out<<<8192,256>>>(pK, pe2_i, pX);                      // X += dw3(P)
        // feed-forward: LN fused into ff1 staging
        k_tmma<1,4,1,1><<<1024,128,TM_SMEM>>>(pX, 64, fw1_i, 256, 0, nullptr, lng_i, lnb_i, pH1, 256);
        k_dw3_gelu<<<32768,256>>>(pH1, fdw_i, pH2, 8);
        k_tmma<4,1,2,0><<<1024,128,TM_SMEM>>>(pH2, 256, fw2_i, 64, 0, nullptr, nullptr, nullptr, pX, 64);
    }

    k_nhwc2nchw<<<tg,256>>>(pX, out);
}